// round 1
// baseline (speedup 1.0000x reference)
#include <cuda_runtime.h>
#include <cstdint>

#define N_NODES 100000
#define N_EDGES 640000
#define HID     128
#define N_LAYERS 3

// ---------------- scratch (static device globals; no allocation) ----------------
__device__ float g_A[(size_t)N_NODES * HID];   // ping
__device__ float g_B[(size_t)N_NODES * HID];   // pong
__device__ float g_S[(size_t)N_NODES * HID];   // support = X @ W
__device__ int   g_cnt[N_NODES];               // per-dst degree, then cursor
__device__ int   g_rowptr[N_NODES];            // CSR row starts (by dst)
__device__ int   g_cursor[N_NODES];            // scatter cursors -> row ends
__device__ int   g_csr_src[N_EDGES];
__device__ float g_csr_val[N_EDGES];
__device__ int   g_blocksums[128];             // scan partials (98 used)

// ---------------- CSR build ----------------
__global__ void hist_kernel(const int* __restrict__ dst) {
    int e = blockIdx.x * blockDim.x + threadIdx.x;
    if (e < N_EDGES) atomicAdd(&g_cnt[dst[e]], 1);
}

// per-block exclusive scan of 1024 counts
__global__ void scan1_kernel() {
    __shared__ int sh[1024];
    int tid = threadIdx.x;
    int i = blockIdx.x * 1024 + tid;
    int v = (i < N_NODES) ? g_cnt[i] : 0;
    sh[tid] = v;
    __syncthreads();
    for (int off = 1; off < 1024; off <<= 1) {
        int t = (tid >= off) ? sh[tid - off] : 0;
        __syncthreads();
        sh[tid] += t;
        __syncthreads();
    }
    if (i < N_NODES) g_rowptr[i] = sh[tid] - v;   // exclusive
    if (tid == 1023) g_blocksums[blockIdx.x] = sh[1023];
}

__global__ void scan2_kernel(int nblocks) {
    if (threadIdx.x == 0) {
        int run = 0;
        for (int b = 0; b < nblocks; b++) {
            int t = g_blocksums[b];
            g_blocksums[b] = run;
            run += t;
        }
    }
}

__global__ void scan3_kernel() {
    int i = blockIdx.x * 1024 + threadIdx.x;
    if (i < N_NODES) {
        int r = g_rowptr[i] + g_blocksums[blockIdx.x];
        g_rowptr[i] = r;
        g_cursor[i] = r;   // init cursors
    }
}

__global__ void scatter_kernel(const int* __restrict__ src,
                               const int* __restrict__ dst,
                               const float* __restrict__ val) {
    int e = blockIdx.x * blockDim.x + threadIdx.x;
    if (e < N_EDGES) {
        int d = dst[e];
        int pos = atomicAdd(&g_cursor[d], 1);
        g_csr_src[pos] = src[e];
        g_csr_val[pos] = val[e];
    }
}

// ---------------- embedding concat ----------------
// one thread per (node, float4-chunk), 32 chunks of 4 floats per node
__global__ void embed_kernel(const int* __restrict__ nodef,
                             const int* __restrict__ typef,
                             const int* __restrict__ lenf,
                             const int* __restrict__ lanef,
                             const float* __restrict__ node_emb,
                             const float* __restrict__ type_emb,
                             const float* __restrict__ len_emb,
                             const float* __restrict__ lane_emb) {
    int u = blockIdx.x * blockDim.x + threadIdx.x;
    if (u >= N_NODES * 32) return;
    int n = u >> 5;
    int c = u & 31;        // float4 chunk within the 128-wide row
    float4 v;
    if (c < 4) {
        int f = lanef[n];
        v = reinterpret_cast<const float4*>(lane_emb + (size_t)f * 16)[c];
    } else if (c < 12) {
        int f = typef[n];
        v = reinterpret_cast<const float4*>(type_emb + (size_t)f * 32)[c - 4];
    } else if (c < 16) {
        int f = lenf[n];
        v = reinterpret_cast<const float4*>(len_emb + (size_t)f * 16)[c - 12];
    } else {
        int f = nodef[n];
        v = reinterpret_cast<const float4*>(node_emb + (size_t)f * 64)[c - 16];
    }
    reinterpret_cast<float4*>(g_A)[u] = v;
}

// ---------------- GEMM: S[r][c] = sum_k X[r][k]*W[k][c]  (M=N_NODES, K=N=128) ----------------
// block: 256 threads (32x8), tile 64 rows x 128 cols; W fully in shared.
__global__ void gemm_kernel(const float* __restrict__ X,
                            const float* __restrict__ W,
                            float* __restrict__ S) {
    extern __shared__ float sh[];
    float* ws = sh;                 // 128*128
    float* xs = sh + 128 * 128;     // 64*128
    int tid = threadIdx.x;
    int row0 = blockIdx.x * 64;

    // load W (128x128) : 4096 float4 by 256 threads
    for (int i = tid; i < 128 * 128 / 4; i += 256)
        reinterpret_cast<float4*>(ws)[i] = reinterpret_cast<const float4*>(W)[i];
    // load X tile (64x128) : 2048 float4
    for (int i = tid; i < 64 * 128 / 4; i += 256) {
        int r = i >> 5;                 // /32 float4 per row
        int gr = row0 + r;
        float4 v = make_float4(0.f, 0.f, 0.f, 0.f);
        if (gr < N_NODES)
            v = reinterpret_cast<const float4*>(X + (size_t)gr * 128)[i & 31];
        reinterpret_cast<float4*>(xs)[i] = v;
    }
    __syncthreads();

    int tx = tid & 31;      // col group
    int ty = tid >> 5;      // row group (0..7)
    float acc[8][4];
#pragma unroll
    for (int i = 0; i < 8; i++)
#pragma unroll
        for (int j = 0; j < 4; j++) acc[i][j] = 0.f;

#pragma unroll 4
    for (int k = 0; k < 128; k++) {
        float wv[4];
#pragma unroll
        for (int j = 0; j < 4; j++) wv[j] = ws[k * 128 + tx + 32 * j];
#pragma unroll
        for (int i = 0; i < 8; i++) {
            float xv = xs[(ty + 8 * i) * 128 + k];
#pragma unroll
            for (int j = 0; j < 4; j++) acc[i][j] = fmaf(xv, wv[j], acc[i][j]);
        }
    }

#pragma unroll
    for (int i = 0; i < 8; i++) {
        int gr = row0 + ty + 8 * i;
        if (gr < N_NODES) {
            float* out = S + (size_t)gr * 128;
#pragma unroll
            for (int j = 0; j < 4; j++) out[tx + 32 * j] = acc[i][j];
        }
    }
}

// ---------------- aggregation: out[d] = b + sum_{e: dst=d} val_e * S[src_e] ----------------
// one warp per node, float4 accumulators (lane covers 4 consecutive cols)
__global__ void agg_kernel(const float* __restrict__ S,
                           const float* __restrict__ b,
                           float* __restrict__ out) {
    int warp = (blockIdx.x * blockDim.x + threadIdx.x) >> 5;
    int lane = threadIdx.x & 31;
    if (warp >= N_NODES) return;
    float4 acc = reinterpret_cast<const float4*>(b)[lane];
    int s = g_rowptr[warp];
    int e = g_cursor[warp];      // cursor == row end after scatter
    for (int j = s; j < e; j++) {
        int src = __ldg(&g_csr_src[j]);
        float v = __ldg(&g_csr_val[j]);
        float4 x = reinterpret_cast<const float4*>(S + (size_t)src * 128)[lane];
        acc.x = fmaf(v, x.x, acc.x);
        acc.y = fmaf(v, x.y, acc.y);
        acc.z = fmaf(v, x.z, acc.z);
        acc.w = fmaf(v, x.w, acc.w);
    }
    reinterpret_cast<float4*>(out + (size_t)warp * 128)[lane] = acc;
}

// ---------------- launch ----------------
extern "C" void kernel_launch(void* const* d_in, const int* in_sizes, int n_in,
                              void* d_out, int out_size) {
    const int*   nodef    = (const int*)d_in[0];
    const int*   typef    = (const int*)d_in[1];
    const int*   lenf     = (const int*)d_in[2];
    const int*   lanef    = (const int*)d_in[3];
    const int*   adj_src  = (const int*)d_in[4];
    const int*   adj_dst  = (const int*)d_in[5];
    const float* adj_val  = (const float*)d_in[6];
    const float* node_emb = (const float*)d_in[7];
    const float* type_emb = (const float*)d_in[8];
    const float* len_emb  = (const float*)d_in[9];
    const float* lane_emb = (const float*)d_in[10];
    const float* W        = (const float*)d_in[11];
    const float* b        = (const float*)d_in[12];
    float* out = (float*)d_out;

    float *pA, *pB, *pS;
    int* pcnt;
    cudaGetSymbolAddress((void**)&pA, g_A);
    cudaGetSymbolAddress((void**)&pB, g_B);
    cudaGetSymbolAddress((void**)&pS, g_S);
    cudaGetSymbolAddress((void**)&pcnt, g_cnt);

    const int smem_gemm = (128 * 128 + 64 * 128) * 4;   // 96 KB
    cudaFuncSetAttribute(gemm_kernel, cudaFuncAttributeMaxDynamicSharedMemorySize, smem_gemm);

    // ---- CSR build (once per launch; reused by all 3 layers) ----
    cudaMemsetAsync(pcnt, 0, N_NODES * sizeof(int));
    hist_kernel<<<(N_EDGES + 255) / 256, 256>>>(adj_dst);
    const int nscan = (N_NODES + 1023) / 1024;          // 98
    scan1_kernel<<<nscan, 1024>>>();
    scan2_kernel<<<1, 32>>>(nscan);
    scan3_kernel<<<nscan, 1024>>>();
    scatter_kernel<<<(N_EDGES + 255) / 256, 256>>>(adj_src, adj_dst, adj_val);

    // ---- embedding concat -> A ----
    embed_kernel<<<(N_NODES * 32 + 255) / 256, 256>>>(nodef, typef, lenf, lanef,
                                                      node_emb, type_emb, len_emb, lane_emb);

    // ---- 3 shared-weight SPGCN layers ----
    const int gemm_blocks = (N_NODES + 63) / 64;
    const int agg_blocks  = (N_NODES * 32 + 255) / 256;

    // layer 0: A -> S -> B
    gemm_kernel<<<gemm_blocks, 256, smem_gemm>>>(pA, W, pS);
    agg_kernel<<<agg_blocks, 256>>>(pS, b, pB);
    // layer 1: B -> S -> A
    gemm_kernel<<<gemm_blocks, 256, smem_gemm>>>(pB, W, pS);
    agg_kernel<<<agg_blocks, 256>>>(pS, b, pA);
    // layer 2: A -> S -> out
    gemm_kernel<<<gemm_blocks, 256, smem_gemm>>>(pA, W, pS);
    agg_kernel<<<agg_blocks, 256>>>(pS, b, out);
}